// round 15
// baseline (speedup 1.0000x reference)
#include <cuda_runtime.h>

#define B_ 32
#define S_ 4096
#define H_ 1024
#define NSPANS_ 16
#define NCLS_ 25
#define H4_ (H_ / 4)      // 256 float4 per row
#define CHUNK_ 16         // tokens per pool block
#define NCHUNK_ 4         // ceil(63 / CHUNK_)
#define ROWS_ 4           // batch rows per fc1 block
#define NBG_ (B_ / ROWS_) // 8 b-groups
#define NFC1_ (32 * NBG_) // 256 fc1 blocks
#define NKQ_ 16           // in-block k-splits
#define KQL_ (H_ / NKQ_)  // 64 k per split
#define KT_ 8             // k-rows per tile iteration
#define NIT_ (KQL_ / KT_) // 8 iterations

// Persistent scratch. Zero-initialized at load; the fc1 epilogue restores
// zeros at the end of every call, so each invocation sees identical state.
__device__ float g_pooled[B_ * H_];
__device__ float g_logits[B_ * NCLS_];
__device__ unsigned g_cnt;

__device__ __forceinline__ void f4add(float4& a, const float4 b) {
    a.x += b.x; a.y += b.y; a.z += b.z; a.w += b.w;
}

// ---------------------------------------------------------------------------
// Kernel 1: span gather-sum. grid (NCHUNK, NSPANS, B), block 256.
// (R12/R14 version: barrier-free decode, predicated gather, f4 atomic.)
// ---------------------------------------------------------------------------
__global__ void __launch_bounds__(256)
pool_kernel(const float* __restrict__ emb,
            const int* __restrict__ spans,
            float* __restrict__ pooled) {
    const int b = blockIdx.z;
    const int n = blockIdx.y;
    const int c = blockIdx.x;

    // Every thread decodes the span (uniform addresses -> broadcast loads).
    const int* row = spans + b * (NSPANS_ * 2);
    const int s_raw = row[2 * n];
    const int e_raw = row[2 * n + 1];
    int v = !(s_raw == 0 && e_raw == 0);
    #pragma unroll
    for (int m = 0; m < NSPANS_ - 1; m++) {          // torch 'break' semantics
        if (m < n && row[2 * m] == 0 && row[2 * m + 1] == 0) v = 0;
    }
    const int s = s_raw + c * CHUNK_;
    const int e = (s + CHUNK_ < e_raw) ? s + CHUNK_ : e_raw;

    if (v && s < e_raw) {
        const float4* base =
            (const float4*)emb + (size_t)b * S_ * H4_ + threadIdx.x;
        float4 a0 = {0,0,0,0}, a1 = {0,0,0,0}, a2 = {0,0,0,0}, a3 = {0,0,0,0};
        const int len = e - s;                 // 1..16
        #pragma unroll
        for (int u = 0; u < CHUNK_; u += 4) {  // predicated, up to 16 in flight
            if (u + 0 < len) f4add(a0, base[(size_t)(s + u + 0) * H4_]);
            if (u + 1 < len) f4add(a1, base[(size_t)(s + u + 1) * H4_]);
            if (u + 2 < len) f4add(a2, base[(size_t)(s + u + 2) * H4_]);
            if (u + 3 < len) f4add(a3, base[(size_t)(s + u + 3) * H4_]);
        }
        f4add(a0, a1); f4add(a2, a3); f4add(a0, a2);
        atomicAdd((float4*)(pooled + b * H_ + threadIdx.x * 4), a0);
    }

    cudaTriggerProgrammaticLaunchCompletion();
}

// ---------------------------------------------------------------------------
// Kernel 2: fc1, grid 256 (bg = tile&7 of 4 rows, jt = tile>>3), 512 thr,
// __launch_bounds__(512,2) -> 2 blocks/SM, 8 warps/SMSP.
// 16 warps = 16-way split-K (kq: 64 k each). Thread: 1 j x 4 batches;
// every W scalar LDS feeds 4 FMAs. Double-buffered KT=8 tiles, 8 barriers.
// Split-K closed via float4 smem exchange; warp kq==0 runs relu +
// fc2-partial; last-ticket block: sigmoid + state re-zero.
// ---------------------------------------------------------------------------
__global__ void __launch_bounds__(512, 2)
fc1_kernel(const int* __restrict__ spans,
           const float* __restrict__ W1,
           const float* __restrict__ b1,
           const float* __restrict__ W2,
           const float* __restrict__ b2,
           float* __restrict__ out) {
    const int tile = blockIdx.x;
    const int bg = tile & 7;          // b-group of 4 rows
    const int jt = tile >> 3;         // j-tile 0..31
    const int tid = threadIdx.x;
    const int lane = tid & 31;
    const int kq = tid >> 5;          // warp = k-split 0..15
    const int j = jt * 32 + lane;

    __shared__ float wt[2][NKQ_][KT_][32];       // 32 KB W1 tiles
    __shared__ float pt[2][NKQ_][ROWS_][KT_];    // 4 KB pooled tiles
    __shared__ float4 red4[NKQ_ - 1][32];        // 7.5 KB split-K exchange
    __shared__ float s_inv[ROWS_];
    __shared__ unsigned s_ticket;

    // ----- pool-independent prologue (overlaps with pool via PDL) -----------
    if (tid < ROWS_) {
        const int* row = spans + (bg * ROWS_ + tid) * (NSPANS_ * 2);
        int total = 0;
        #pragma unroll
        for (int m = 0; m < NSPANS_; m++) {
            int a = row[2 * m], e = row[2 * m + 1];
            if (a == 0 && e == 0) break;
            total += e - a;
        }
        s_inv[tid] = 1.0f / (float)total;
    }

    // W stage = 16 kq x 8 k-rows x 8 f4-cols = 1024 float4; 2 per thread.
    const int f = tid * 2;
    const int wq = f >> 6;             // kq 0..15
    const int wr = (f >> 3) & 7;       // k-row 0..7
    const int wc = (f & 7) * 4;        // float col 0,4,..,28
    const float* wsrc = W1 + (size_t)(wq * KQL_ + wr) * H_ + jt * 32 + wc;
    // p stage = 16 kq x 4 rows x 2 f4 = 128 float4; tid<128 one each.
    const int pq = tid >> 3;           // kq 0..15
    const int pr = (tid >> 1) & 3;     // row 0..3
    const int pk = (tid & 1) * 4;      // k offset 0,4
    const float* psrc =
        g_pooled + (size_t)(bg * ROWS_ + pr) * H_ + pq * KQL_ + pk;

    // W1 tile 0 fetch (independent of pool)
    float4 rw0 = *(const float4*)(wsrc);
    float4 rw1 = *(const float4*)(wsrc + 4);
    *(float4*)&wt[0][wq][wr][wc] = rw0;
    *(float4*)&wt[0][wq][wr][wc + 4] = rw1;

    // ----- wait for pool grid's writes to be visible ------------------------
    cudaGridDependencySynchronize();

    float4 rp;
    if (tid < 128) {
        rp = __ldcg((const float4*)psrc);
        *(float4*)&pt[0][pq][pr][pk] = rp;
    }
    __syncthreads();

    // 8 accumulator chains: (batch 0..3) x (chain A/B)
    float cA0 = 0.f, cB0 = 0.f, cA1 = 0.f, cB1 = 0.f;
    float cA2 = 0.f, cB2 = 0.f, cA3 = 0.f, cB3 = 0.f;

    #pragma unroll 1
    for (int t = 0; t < NIT_; t++) {
        if (t + 1 < NIT_) {
            rw0 = *(const float4*)(wsrc + (size_t)(t + 1) * KT_ * H_);
            rw1 = *(const float4*)(wsrc + (size_t)(t + 1) * KT_ * H_ + 4);
            if (tid < 128)
                rp = __ldcg((const float4*)(psrc + (t + 1) * KT_));
        }

        const float* wk = &wt[t & 1][kq][0][lane];
        const float4* p0 = (const float4*)&pt[t & 1][kq][0][0];
        const float4* p1 = (const float4*)&pt[t & 1][kq][1][0];
        const float4* p2 = (const float4*)&pt[t & 1][kq][2][0];
        const float4* p3 = (const float4*)&pt[t & 1][kq][3][0];
        #pragma unroll
        for (int kk = 0; kk < KT_ / 4; kk++) {     // 2 groups of 4 k
            const float4 x0 = p0[kk];
            const float4 x1 = p1[kk];
            const float4 x2 = p2[kk];
            const float4 x3 = p3[kk];
            const float w0 = wk[(4 * kk + 0) * 32];
            const float w1 = wk[(4 * kk + 1) * 32];
            const float w2 = wk[(4 * kk + 2) * 32];
            const float w3 = wk[(4 * kk + 3) * 32];
            cA0 = fmaf(x0.x, w0, cA0); cB0 = fmaf(x0.y, w1, cB0);
            cA1 = fmaf(x1.x, w0, cA1); cB1 = fmaf(x1.y, w1, cB1);
            cA2 = fmaf(x2.x, w0, cA2); cB2 = fmaf(x2.y, w1, cB2);
            cA3 = fmaf(x3.x, w0, cA3); cB3 = fmaf(x3.y, w1, cB3);
            cA0 = fmaf(x0.z, w2, cA0); cB0 = fmaf(x0.w, w3, cB0);
            cA1 = fmaf(x1.z, w2, cA1); cB1 = fmaf(x1.w, w3, cB1);
            cA2 = fmaf(x2.z, w2, cA2); cB2 = fmaf(x2.w, w3, cB2);
            cA3 = fmaf(x3.z, w2, cA3); cB3 = fmaf(x3.w, w3, cB3);
        }

        if (t + 1 < NIT_) {
            *(float4*)&wt[(t + 1) & 1][wq][wr][wc] = rw0;
            *(float4*)&wt[(t + 1) & 1][wq][wr][wc + 4] = rw1;
            if (tid < 128) *(float4*)&pt[(t + 1) & 1][pq][pr][pk] = rp;
        }
        __syncthreads();
    }
    float d0 = cA0 + cB0;   // batch bg*4 + 0 partial (this k-split)
    float d1 = cA1 + cB1;
    float d2 = cA2 + cB2;
    float d3 = cA3 + cB3;

    // close 16-way split-K
    if (kq != 0) red4[kq - 1][lane] = make_float4(d0, d1, d2, d3);
    __syncthreads();
    if (kq == 0) {
        #pragma unroll
        for (int q = 0; q < NKQ_ - 1; q++) {
            const float4 r = red4[q][lane];
            d0 += r.x; d1 += r.y; d2 += r.z; d3 += r.w;
        }
        const float bias = b1[j];
        const int brow0 = bg * ROWS_;
        const float h0 = fmaxf(fmaf(d0, s_inv[0], bias), 0.f);
        const float h1 = fmaxf(fmaf(d1, s_inv[1], bias), 0.f);
        const float h2 = fmaxf(fmaf(d2, s_inv[2], bias), 0.f);
        const float h3 = fmaxf(fmaf(d3, s_inv[3], bias), 0.f);

        // fc2 partial for 4 batches
        float acc0 = 0.f, acc1 = 0.f, acc2 = 0.f, acc3 = 0.f;
        const int jbase = jt * 32;
        #pragma unroll
        for (int l = 0; l < 32; l++) {
            const float hv0 = __shfl_sync(0xffffffffu, h0, l);
            const float hv1 = __shfl_sync(0xffffffffu, h1, l);
            const float hv2 = __shfl_sync(0xffffffffu, h2, l);
            const float hv3 = __shfl_sync(0xffffffffu, h3, l);
            if (lane < NCLS_) {
                const float wv = W2[(jbase + l) * NCLS_ + lane];
                acc0 = fmaf(hv0, wv, acc0);
                acc1 = fmaf(hv1, wv, acc1);
                acc2 = fmaf(hv2, wv, acc2);
                acc3 = fmaf(hv3, wv, acc3);
            }
        }
        if (lane < NCLS_) {
            atomicAdd(g_logits + (brow0 + 0) * NCLS_ + lane, acc0);
            atomicAdd(g_logits + (brow0 + 1) * NCLS_ + lane, acc1);
            atomicAdd(g_logits + (brow0 + 2) * NCLS_ + lane, acc2);
            atomicAdd(g_logits + (brow0 + 3) * NCLS_ + lane, acc3);
        }
    }

    // ---- ticket: the block drawing NFC1_-1 is provably last; no spin -------
    __threadfence();
    __syncthreads();
    if (tid == 0) s_ticket = atomicAdd(&g_cnt, 1u);
    __syncthreads();
    if (s_ticket != (unsigned)(NFC1_ - 1)) return;

    // ---- epilogue: sigmoid + restore zero state -----------------------------
    for (int idx = tid; idx < B_ * NCLS_; idx += 512) {
        const float v = __ldcg(g_logits + idx) + b2[idx % NCLS_];
        out[idx] = 1.f / (1.f + __expf(-v));
        g_logits[idx] = 0.f;
    }
    {
        float4* pz = (float4*)g_pooled;
        for (int k = tid; k < B_ * H4_; k += 512)
            pz[k] = make_float4(0.f, 0.f, 0.f, 0.f);
    }
    if (tid == 0) g_cnt = 0u;
}

// ---------------------------------------------------------------------------
extern "C" void kernel_launch(void* const* d_in, const int* in_sizes, int n_in,
                              void* d_out, int out_size) {
    const float* all_emb = (const float*)d_in[0];
    const int*   spans   = (const int*)d_in[1];
    const float* W1      = (const float*)d_in[2];
    const float* b1      = (const float*)d_in[3];
    const float* W2      = (const float*)d_in[4];
    const float* b2      = (const float*)d_in[5];
    float* out = (float*)d_out;

    float* pooled;
    cudaGetSymbolAddress((void**)&pooled, g_pooled);

    {
        dim3 grid(NCHUNK_, NSPANS_, B_);
        pool_kernel<<<grid, 256>>>(all_emb, spans, pooled);
    }
    {
        cudaLaunchConfig_t cfg = {};
        cfg.gridDim = dim3(NFC1_, 1, 1);
        cfg.blockDim = dim3(512, 1, 1);
        cfg.dynamicSmemBytes = 0;
        cfg.stream = 0;
        cudaLaunchAttribute attrs[1];
        attrs[0].id = cudaLaunchAttributeProgrammaticStreamSerialization;
        attrs[0].val.programmaticStreamSerializationAllowed = 1;
        cfg.attrs = attrs;
        cfg.numAttrs = 1;
        cudaLaunchKernelEx(&cfg, fc1_kernel, spans, W1, b1, W2, b2, out);
    }
}

// round 16
// speedup vs baseline: 1.1792x; 1.1792x over previous
#include <cuda_runtime.h>

#define B_ 32
#define S_ 4096
#define H_ 1024
#define NSPANS_ 16
#define NCLS_ 25
#define H4_ (H_ / 4)      // 256 float4 per row
#define CHUNK_ 16         // tokens per pool block
#define NCHUNK_ 4         // ceil(63 / CHUNK_)
#define ROWS_ 8           // batch rows per fc1 block
#define NFC1_ 128         // 32 j-tiles x 4 b-groups
#define NKQ_ 8            // k-splits (one warp pair each)
#define KQL_ (H_ / NKQ_)  // 128 k per split

// Persistent scratch. Zero-initialized at load; the fc1 epilogue restores
// zeros at the end of every call, so each invocation sees identical state.
__device__ float g_pooled[B_ * H_];
__device__ float g_logits[B_ * NCLS_];
__device__ unsigned g_cnt;

__device__ __forceinline__ void f4add(float4& a, const float4 b) {
    a.x += b.x; a.y += b.y; a.z += b.z; a.w += b.w;
}

// ---------------------------------------------------------------------------
// Kernel 1: span gather-sum. grid (NCHUNK, NSPANS, B), block 256.
// (R12/R14 version: barrier-free decode, predicated gather, f4 atomic.)
// ---------------------------------------------------------------------------
__global__ void __launch_bounds__(256)
pool_kernel(const float* __restrict__ emb,
            const int* __restrict__ spans,
            float* __restrict__ pooled) {
    const int b = blockIdx.z;
    const int n = blockIdx.y;
    const int c = blockIdx.x;

    // Every thread decodes the span (uniform addresses -> broadcast loads).
    const int* row = spans + b * (NSPANS_ * 2);
    const int s_raw = row[2 * n];
    const int e_raw = row[2 * n + 1];
    int v = !(s_raw == 0 && e_raw == 0);
    #pragma unroll
    for (int m = 0; m < NSPANS_ - 1; m++) {          // torch 'break' semantics
        if (m < n && row[2 * m] == 0 && row[2 * m + 1] == 0) v = 0;
    }
    const int s = s_raw + c * CHUNK_;
    const int e = (s + CHUNK_ < e_raw) ? s + CHUNK_ : e_raw;

    if (v && s < e_raw) {
        const float4* base =
            (const float4*)emb + (size_t)b * S_ * H4_ + threadIdx.x;
        float4 a0 = {0,0,0,0}, a1 = {0,0,0,0}, a2 = {0,0,0,0}, a3 = {0,0,0,0};
        const int len = e - s;                 // 1..16
        #pragma unroll
        for (int u = 0; u < CHUNK_; u += 4) {  // predicated, up to 16 in flight
            if (u + 0 < len) f4add(a0, base[(size_t)(s + u + 0) * H4_]);
            if (u + 1 < len) f4add(a1, base[(size_t)(s + u + 1) * H4_]);
            if (u + 2 < len) f4add(a2, base[(size_t)(s + u + 2) * H4_]);
            if (u + 3 < len) f4add(a3, base[(size_t)(s + u + 3) * H4_]);
        }
        f4add(a0, a1); f4add(a2, a3); f4add(a0, a2);
        atomicAdd((float4*)(pooled + b * H_ + threadIdx.x * 4), a0);
    }

    cudaTriggerProgrammaticLaunchCompletion();
}

// ---------------------------------------------------------------------------
// fc1 shared-memory layout (dynamic, ~168 KB)
// ---------------------------------------------------------------------------
struct FC1Smem {
    float wt[H_][32];           // 128 KB: full W1 slice [k][j-lane]
    float pt[ROWS_][H_];        // 32 KB: all 8 pooled rows [row][k]
    float4 red4[NKQ_ - 1][2][32];  // split-K exchange
    float s_inv[ROWS_];
    unsigned s_ticket;
};

// ---------------------------------------------------------------------------
// Kernel 2: fc1, grid 128 (bg = tile&3 of 8 rows, jt = tile>>2), 512 thr.
// Single-shot staging of the whole W1 slice + pooled rows (MLP ~20/thread),
// ONE barrier, then a completely barrier-free 512-FMA/thread dot.
// Warps: kq = ty&7 (128 k each), bh = ty>>3 (4 batches each).
// Split-K closed via smem; kq==0 warps run relu + fc2-partial;
// last-ticket block: sigmoid + state re-zero.  (Epilogue = R14 verbatim.)
// ---------------------------------------------------------------------------
__global__ void __launch_bounds__(512)
fc1_kernel(const int* __restrict__ spans,
           const float* __restrict__ W1,
           const float* __restrict__ b1,
           const float* __restrict__ W2,
           const float* __restrict__ b2,
           float* __restrict__ out) {
    extern __shared__ char smem_raw[];
    FC1Smem* sm = (FC1Smem*)smem_raw;

    const int tile = blockIdx.x;
    const int bg = tile & 3;
    const int jt = tile >> 2;
    const int tid = threadIdx.x;
    const int lane = tid & 31;
    const int ty = tid >> 5;          // 0..15
    const int kq = ty & 7;            // k-split 0..7 (128 k each)
    const int bh = ty >> 3;           // batch-half 0..1 (4 rows each)
    const int j = jt * 32 + lane;

    // ----- pool-independent prologue ----------------------------------------
    if (tid < ROWS_) {
        const int* row = spans + (bg * ROWS_ + tid) * (NSPANS_ * 2);
        int total = 0;
        #pragma unroll
        for (int m = 0; m < NSPANS_; m++) {
            int a = row[2 * m], e = row[2 * m + 1];
            if (a == 0 && e == 0) break;
            total += e - a;
        }
        sm->s_inv[tid] = 1.0f / (float)total;
    }

    // ----- stage full W1 slice: 8192 float4, 16 per thread (pool-indep) -----
    {
        const float* wbase = W1 + jt * 32;
        #pragma unroll
        for (int r = 0; r < 16; r++) {
            const int idx = tid + 512 * r;        // 0..8191
            const int k = idx >> 3;               // k-row 0..1023
            const int cg = (idx & 7) * 4;         // j col 0,4,..,28
            *(float4*)&sm->wt[k][cg] =
                *(const float4*)(wbase + (size_t)k * H_ + cg);
        }
    }

    // ----- wait for pool grid's writes, then stage pooled rows --------------
    cudaGridDependencySynchronize();
    {
        #pragma unroll
        for (int r = 0; r < 4; r++) {
            const int idx = tid + 512 * r;        // 0..2047 float4
            const int row = idx >> 8;             // 0..7
            const int k4 = (idx & 255) * 4;       // k 0..1020
            *(float4*)&sm->pt[row][k4] = __ldcg(
                (const float4*)(g_pooled + (size_t)(bg * ROWS_ + row) * H_ + k4));
        }
    }
    __syncthreads();   // the ONE barrier before compute

    // ----- barrier-free dot: 1 j x 4 batches x 128 k per thread -------------
    const int k0 = kq * KQL_;
    const int r0 = bh * 4;
    float cA0 = 0.f, cB0 = 0.f, cA1 = 0.f, cB1 = 0.f;
    float cA2 = 0.f, cB2 = 0.f, cA3 = 0.f, cB3 = 0.f;

    #pragma unroll 8
    for (int k = 0; k < KQL_; k += 4) {
        const float w0 = sm->wt[k0 + k + 0][lane];
        const float w1 = sm->wt[k0 + k + 1][lane];
        const float w2 = sm->wt[k0 + k + 2][lane];
        const float w3 = sm->wt[k0 + k + 3][lane];
        const float4 x0 = *(const float4*)&sm->pt[r0 + 0][k0 + k];
        const float4 x1 = *(const float4*)&sm->pt[r0 + 1][k0 + k];
        const float4 x2 = *(const float4*)&sm->pt[r0 + 2][k0 + k];
        const float4 x3 = *(const float4*)&sm->pt[r0 + 3][k0 + k];
        cA0 = fmaf(x0.x, w0, cA0); cB0 = fmaf(x0.y, w1, cB0);
        cA1 = fmaf(x1.x, w0, cA1); cB1 = fmaf(x1.y, w1, cB1);
        cA2 = fmaf(x2.x, w0, cA2); cB2 = fmaf(x2.y, w1, cB2);
        cA3 = fmaf(x3.x, w0, cA3); cB3 = fmaf(x3.y, w1, cB3);
        cA0 = fmaf(x0.z, w2, cA0); cB0 = fmaf(x0.w, w3, cB0);
        cA1 = fmaf(x1.z, w2, cA1); cB1 = fmaf(x1.w, w3, cB1);
        cA2 = fmaf(x2.z, w2, cA2); cB2 = fmaf(x2.w, w3, cB2);
        cA3 = fmaf(x3.z, w2, cA3); cB3 = fmaf(x3.w, w3, cB3);
    }
    float d0 = cA0 + cB0;   // batch bg*8 + bh*4 + 0 partial (this k-split)
    float d1 = cA1 + cB1;
    float d2 = cA2 + cB2;
    float d3 = cA3 + cB3;

    // close 8-way split-K
    if (kq != 0) sm->red4[kq - 1][bh][lane] = make_float4(d0, d1, d2, d3);
    __syncthreads();
    if (kq == 0) {
        #pragma unroll
        for (int q = 0; q < NKQ_ - 1; q++) {
            const float4 r = sm->red4[q][bh][lane];
            d0 += r.x; d1 += r.y; d2 += r.z; d3 += r.w;
        }
        const float bias = b1[j];
        const int brow0 = bg * ROWS_ + bh * 4;
        const float h0 = fmaxf(fmaf(d0, sm->s_inv[bh * 4 + 0], bias), 0.f);
        const float h1 = fmaxf(fmaf(d1, sm->s_inv[bh * 4 + 1], bias), 0.f);
        const float h2 = fmaxf(fmaf(d2, sm->s_inv[bh * 4 + 2], bias), 0.f);
        const float h3 = fmaxf(fmaf(d3, sm->s_inv[bh * 4 + 3], bias), 0.f);

        // fc2 partial for 4 batches
        float acc0 = 0.f, acc1 = 0.f, acc2 = 0.f, acc3 = 0.f;
        const int jbase = jt * 32;
        #pragma unroll
        for (int l = 0; l < 32; l++) {
            const float hv0 = __shfl_sync(0xffffffffu, h0, l);
            const float hv1 = __shfl_sync(0xffffffffu, h1, l);
            const float hv2 = __shfl_sync(0xffffffffu, h2, l);
            const float hv3 = __shfl_sync(0xffffffffu, h3, l);
            if (lane < NCLS_) {
                const float wv = W2[(jbase + l) * NCLS_ + lane];
                acc0 = fmaf(hv0, wv, acc0);
                acc1 = fmaf(hv1, wv, acc1);
                acc2 = fmaf(hv2, wv, acc2);
                acc3 = fmaf(hv3, wv, acc3);
            }
        }
        if (lane < NCLS_) {
            atomicAdd(g_logits + (brow0 + 0) * NCLS_ + lane, acc0);
            atomicAdd(g_logits + (brow0 + 1) * NCLS_ + lane, acc1);
            atomicAdd(g_logits + (brow0 + 2) * NCLS_ + lane, acc2);
            atomicAdd(g_logits + (brow0 + 3) * NCLS_ + lane, acc3);
        }
    }

    // ---- ticket: the block drawing NFC1_-1 is provably last; no spin -------
    __threadfence();
    __syncthreads();
    if (tid == 0) sm->s_ticket = atomicAdd(&g_cnt, 1u);
    __syncthreads();
    if (sm->s_ticket != (unsigned)(NFC1_ - 1)) return;

    // ---- epilogue: sigmoid + restore zero state -----------------------------
    for (int idx = tid; idx < B_ * NCLS_; idx += 512) {
        const float v = __ldcg(g_logits + idx) + b2[idx % NCLS_];
        out[idx] = 1.f / (1.f + __expf(-v));
        g_logits[idx] = 0.f;
    }
    {
        float4* pz = (float4*)g_pooled;
        for (int k = tid; k < B_ * H4_; k += 512)
            pz[k] = make_float4(0.f, 0.f, 0.f, 0.f);
    }
    if (tid == 0) g_cnt = 0u;
}

// ---------------------------------------------------------------------------
extern "C" void kernel_launch(void* const* d_in, const int* in_sizes, int n_in,
                              void* d_out, int out_size) {
    const float* all_emb = (const float*)d_in[0];
    const int*   spans   = (const int*)d_in[1];
    const float* W1      = (const float*)d_in[2];
    const float* b1      = (const float*)d_in[3];
    const float* W2      = (const float*)d_in[4];
    const float* b2      = (const float*)d_in[5];
    float* out = (float*)d_out;

    float* pooled;
    cudaGetSymbolAddress((void**)&pooled, g_pooled);

    const int smem_bytes = (int)sizeof(FC1Smem);
    cudaFuncSetAttribute(fc1_kernel,
                         cudaFuncAttributeMaxDynamicSharedMemorySize,
                         smem_bytes);

    {
        dim3 grid(NCHUNK_, NSPANS_, B_);
        pool_kernel<<<grid, 256>>>(all_emb, spans, pooled);
    }
    {
        cudaLaunchConfig_t cfg = {};
        cfg.gridDim = dim3(NFC1_, 1, 1);
        cfg.blockDim = dim3(512, 1, 1);
        cfg.dynamicSmemBytes = smem_bytes;
        cfg.stream = 0;
        cudaLaunchAttribute attrs[1];
        attrs[0].id = cudaLaunchAttributeProgrammaticStreamSerialization;
        attrs[0].val.programmaticStreamSerializationAllowed = 1;
        cfg.attrs = attrs;
        cfg.numAttrs = 1;
        cudaLaunchKernelEx(&cfg, fc1_kernel, spans, W1, b1, W2, b2, out);
    }
}

// round 17
// speedup vs baseline: 1.1936x; 1.0122x over previous
#include <cuda_runtime.h>

#define B_ 32
#define S_ 4096
#define H_ 1024
#define NSPANS_ 16
#define NCLS_ 25
#define H4_ (H_ / 4)      // 256 float4 per row
#define CHUNK_ 16         // tokens per pool block
#define NCHUNK_ 4         // ceil(63 / CHUNK_)
#define ROWS_ 8           // batch rows per fc1 block
#define NFC1_ 128         // 32 j-tiles x 4 b-groups
#define NKQ_ 16           // k-splits (one warp each, x2 batch-halves)
#define KQL_ (H_ / NKQ_)  // 64 k per split
#define NTH_ 1024         // fc1 threads per block

// Persistent scratch. Zero-initialized at load; the fc1 epilogue restores
// zeros at the end of every call, so each invocation sees identical state.
__device__ float g_pooled[B_ * H_];
__device__ float g_logits[B_ * NCLS_];
__device__ unsigned g_cnt;

__device__ __forceinline__ void f4add(float4& a, const float4 b) {
    a.x += b.x; a.y += b.y; a.z += b.z; a.w += b.w;
}

// ---------------------------------------------------------------------------
// Kernel 1: span gather-sum. grid (NCHUNK, NSPANS, B), block 256.
// (R12/R14 version: barrier-free decode, predicated gather, f4 atomic.)
// ---------------------------------------------------------------------------
__global__ void __launch_bounds__(256)
pool_kernel(const float* __restrict__ emb,
            const int* __restrict__ spans,
            float* __restrict__ pooled) {
    const int b = blockIdx.z;
    const int n = blockIdx.y;
    const int c = blockIdx.x;

    // Every thread decodes the span (uniform addresses -> broadcast loads).
    const int* row = spans + b * (NSPANS_ * 2);
    const int s_raw = row[2 * n];
    const int e_raw = row[2 * n + 1];
    int v = !(s_raw == 0 && e_raw == 0);
    #pragma unroll
    for (int m = 0; m < NSPANS_ - 1; m++) {          // torch 'break' semantics
        if (m < n && row[2 * m] == 0 && row[2 * m + 1] == 0) v = 0;
    }
    const int s = s_raw + c * CHUNK_;
    const int e = (s + CHUNK_ < e_raw) ? s + CHUNK_ : e_raw;

    if (v && s < e_raw) {
        const float4* base =
            (const float4*)emb + (size_t)b * S_ * H4_ + threadIdx.x;
        float4 a0 = {0,0,0,0}, a1 = {0,0,0,0}, a2 = {0,0,0,0}, a3 = {0,0,0,0};
        const int len = e - s;                 // 1..16
        #pragma unroll
        for (int u = 0; u < CHUNK_; u += 4) {  // predicated, up to 16 in flight
            if (u + 0 < len) f4add(a0, base[(size_t)(s + u + 0) * H4_]);
            if (u + 1 < len) f4add(a1, base[(size_t)(s + u + 1) * H4_]);
            if (u + 2 < len) f4add(a2, base[(size_t)(s + u + 2) * H4_]);
            if (u + 3 < len) f4add(a3, base[(size_t)(s + u + 3) * H4_]);
        }
        f4add(a0, a1); f4add(a2, a3); f4add(a0, a2);
        atomicAdd((float4*)(pooled + b * H_ + threadIdx.x * 4), a0);
    }

    cudaTriggerProgrammaticLaunchCompletion();
}

// ---------------------------------------------------------------------------
// fc1 shared-memory layout (dynamic, ~176 KB)
// ---------------------------------------------------------------------------
struct FC1Smem {
    float wt[H_][32];              // 128 KB: full W1 slice [k][j-lane]
    float pt[ROWS_][H_];           // 32 KB: all 8 pooled rows [row][k]
    float4 red4[NKQ_ - 1][2][32];  // 15 KB split-K exchange
    float s_inv[ROWS_];
    unsigned s_ticket;
};

// ---------------------------------------------------------------------------
// Kernel 2: fc1, grid 128 (bg = tile&3 of 8 rows, jt = tile>>2), 1024 thr
// -> 8 warps/SMSP (the R16 shape was latency-starved at 4).
// Single-shot staging (8 W-f4 + 2 p-f4 per thread), ONE barrier, then a
// barrier-free 256-FMA/thread dot (1 j x 4 batches x 64 k).
// Warps: kq = ty&15 (64 k each), bh = ty>>4 (4 batches each).
// Split-K closed via smem; kq==0 warps run relu + fc2-partial;
// last-ticket block: sigmoid + state re-zero.
// ---------------------------------------------------------------------------
__global__ void __launch_bounds__(NTH_)
fc1_kernel(const int* __restrict__ spans,
           const float* __restrict__ W1,
           const float* __restrict__ b1,
           const float* __restrict__ W2,
           const float* __restrict__ b2,
           float* __restrict__ out) {
    extern __shared__ char smem_raw[];
    FC1Smem* sm = (FC1Smem*)smem_raw;

    const int tile = blockIdx.x;
    const int bg = tile & 3;
    const int jt = tile >> 2;
    const int tid = threadIdx.x;
    const int lane = tid & 31;
    const int ty = tid >> 5;          // 0..31
    const int kq = ty & 15;           // k-split 0..15 (64 k each)
    const int bh = ty >> 4;           // batch-half 0..1 (4 rows each)
    const int j = jt * 32 + lane;

    // ----- pool-independent prologue ----------------------------------------
    if (tid < ROWS_) {
        const int* row = spans + (bg * ROWS_ + tid) * (NSPANS_ * 2);
        int total = 0;
        #pragma unroll
        for (int m = 0; m < NSPANS_; m++) {
            int a = row[2 * m], e = row[2 * m + 1];
            if (a == 0 && e == 0) break;
            total += e - a;
        }
        sm->s_inv[tid] = 1.0f / (float)total;
    }

    // ----- stage full W1 slice: 8192 float4, 8 per thread (pool-indep) ------
    {
        const float* wbase = W1 + jt * 32;
        #pragma unroll
        for (int r = 0; r < 8; r++) {
            const int idx = tid + NTH_ * r;       // 0..8191
            const int k = idx >> 3;               // k-row 0..1023
            const int cg = (idx & 7) * 4;         // j col 0,4,..,28
            *(float4*)&sm->wt[k][cg] =
                *(const float4*)(wbase + (size_t)k * H_ + cg);
        }
    }

    // ----- wait for pool grid's writes, then stage pooled rows --------------
    cudaGridDependencySynchronize();
    {
        #pragma unroll
        for (int r = 0; r < 2; r++) {
            const int idx = tid + NTH_ * r;       // 0..2047 float4
            const int row = idx >> 8;             // 0..7
            const int k4 = (idx & 255) * 4;       // k 0..1020
            *(float4*)&sm->pt[row][k4] = __ldcg(
                (const float4*)(g_pooled + (size_t)(bg * ROWS_ + row) * H_ + k4));
        }
    }
    __syncthreads();   // the ONE barrier before compute

    // ----- barrier-free dot: 1 j x 4 batches x 64 k per thread --------------
    const int k0 = kq * KQL_;
    const int r0 = bh * 4;
    float cA0 = 0.f, cB0 = 0.f, cA1 = 0.f, cB1 = 0.f;
    float cA2 = 0.f, cB2 = 0.f, cA3 = 0.f, cB3 = 0.f;

    #pragma unroll 8
    for (int k = 0; k < KQL_; k += 4) {
        const float w0 = sm->wt[k0 + k + 0][lane];
        const float w1 = sm->wt[k0 + k + 1][lane];
        const float w2 = sm->wt[k0 + k + 2][lane];
        const float w3 = sm->wt[k0 + k + 3][lane];
        const float4 x0 = *(const float4*)&sm->pt[r0 + 0][k0 + k];
        const float4 x1 = *(const float4*)&sm->pt[r0 + 1][k0 + k];
        const float4 x2 = *(const float4*)&sm->pt[r0 + 2][k0 + k];
        const float4 x3 = *(const float4*)&sm->pt[r0 + 3][k0 + k];
        cA0 = fmaf(x0.x, w0, cA0); cB0 = fmaf(x0.y, w1, cB0);
        cA1 = fmaf(x1.x, w0, cA1); cB1 = fmaf(x1.y, w1, cB1);
        cA2 = fmaf(x2.x, w0, cA2); cB2 = fmaf(x2.y, w1, cB2);
        cA3 = fmaf(x3.x, w0, cA3); cB3 = fmaf(x3.y, w1, cB3);
        cA0 = fmaf(x0.z, w2, cA0); cB0 = fmaf(x0.w, w3, cB0);
        cA1 = fmaf(x1.z, w2, cA1); cB1 = fmaf(x1.w, w3, cB1);
        cA2 = fmaf(x2.z, w2, cA2); cB2 = fmaf(x2.w, w3, cB2);
        cA3 = fmaf(x3.z, w2, cA3); cB3 = fmaf(x3.w, w3, cB3);
    }
    float d0 = cA0 + cB0;   // batch bg*8 + bh*4 + 0 partial (this k-split)
    float d1 = cA1 + cB1;
    float d2 = cA2 + cB2;
    float d3 = cA3 + cB3;

    // close 16-way split-K
    if (kq != 0) sm->red4[kq - 1][bh][lane] = make_float4(d0, d1, d2, d3);
    __syncthreads();
    if (kq == 0) {
        #pragma unroll
        for (int q = 0; q < NKQ_ - 1; q++) {
            const float4 r = sm->red4[q][bh][lane];
            d0 += r.x; d1 += r.y; d2 += r.z; d3 += r.w;
        }
        const float bias = b1[j];
        const int brow0 = bg * ROWS_ + bh * 4;
        const float h0 = fmaxf(fmaf(d0, sm->s_inv[bh * 4 + 0], bias), 0.f);
        const float h1 = fmaxf(fmaf(d1, sm->s_inv[bh * 4 + 1], bias), 0.f);
        const float h2 = fmaxf(fmaf(d2, sm->s_inv[bh * 4 + 2], bias), 0.f);
        const float h3 = fmaxf(fmaf(d3, sm->s_inv[bh * 4 + 3], bias), 0.f);

        // fc2 partial for 4 batches
        float acc0 = 0.f, acc1 = 0.f, acc2 = 0.f, acc3 = 0.f;
        const int jbase = jt * 32;
        #pragma unroll
        for (int l = 0; l < 32; l++) {
            const float hv0 = __shfl_sync(0xffffffffu, h0, l);
            const float hv1 = __shfl_sync(0xffffffffu, h1, l);
            const float hv2 = __shfl_sync(0xffffffffu, h2, l);
            const float hv3 = __shfl_sync(0xffffffffu, h3, l);
            if (lane < NCLS_) {
                const float wv = W2[(jbase + l) * NCLS_ + lane];
                acc0 = fmaf(hv0, wv, acc0);
                acc1 = fmaf(hv1, wv, acc1);
                acc2 = fmaf(hv2, wv, acc2);
                acc3 = fmaf(hv3, wv, acc3);
            }
        }
        if (lane < NCLS_) {
            atomicAdd(g_logits + (brow0 + 0) * NCLS_ + lane, acc0);
            atomicAdd(g_logits + (brow0 + 1) * NCLS_ + lane, acc1);
            atomicAdd(g_logits + (brow0 + 2) * NCLS_ + lane, acc2);
            atomicAdd(g_logits + (brow0 + 3) * NCLS_ + lane, acc3);
        }
    }

    // ---- ticket: the block drawing NFC1_-1 is provably last; no spin -------
    __threadfence();
    __syncthreads();
    if (tid == 0) sm->s_ticket = atomicAdd(&g_cnt, 1u);
    __syncthreads();
    if (sm->s_ticket != (unsigned)(NFC1_ - 1)) return;

    // ---- epilogue: sigmoid + restore zero state -----------------------------
    for (int idx = tid; idx < B_ * NCLS_; idx += NTH_) {
        const float v = __ldcg(g_logits + idx) + b2[idx % NCLS_];
        out[idx] = 1.f / (1.f + __expf(-v));
        g_logits[idx] = 0.f;
    }
    {
        float4* pz = (float4*)g_pooled;
        for (int k = tid; k < B_ * H4_; k += NTH_)
            pz[k] = make_float4(0.f, 0.f, 0.f, 0.f);
    }
    if (tid == 0) g_cnt = 0u;
}

// ---------------------------------------------------------------------------
extern "C" void kernel_launch(void* const* d_in, const int* in_sizes, int n_in,
                              void* d_out, int out_size) {
    const float* all_emb = (const float*)d_in[0];
    const int*   spans   = (const int*)d_in[1];
    const float* W1      = (const float*)d_in[2];
    const float* b1      = (const float*)d_in[3];
    const float* W2      = (const float*)d_in[4];
    const float* b2      = (const float*)d_in[5];
    float* out = (float*)d_out;

    float* pooled;
    cudaGetSymbolAddress((void**)&pooled, g_pooled);

    const int smem_bytes = (int)sizeof(FC1Smem);
    cudaFuncSetAttribute(fc1_kernel,
                         cudaFuncAttributeMaxDynamicSharedMemorySize,
                         smem_bytes);

    {
        dim3 grid(NCHUNK_, NSPANS_, B_);
        pool_kernel<<<grid, 256>>>(all_emb, spans, pooled);
    }
    {
        cudaLaunchConfig_t cfg = {};
        cfg.gridDim = dim3(NFC1_, 1, 1);
        cfg.blockDim = dim3(NTH_, 1, 1);
        cfg.dynamicSmemBytes = smem_bytes;
        cfg.stream = 0;
        cudaLaunchAttribute attrs[1];
        attrs[0].id = cudaLaunchAttributeProgrammaticStreamSerialization;
        attrs[0].val.programmaticStreamSerializationAllowed = 1;
        cfg.attrs = attrs;
        cfg.numAttrs = 1;
        cudaLaunchKernelEx(&cfg, fc1_kernel, spans, W1, b1, W2, b2, out);
    }
}